// round 13
// baseline (speedup 1.0000x reference)
#include <cuda_runtime.h>
#include <math_constants.h>

#define NP 100000          // nodes per type (N_P == N_A)
#define EDGES 500000
#define HD 128             // H*D
#define NH 4               // heads
#define PAD 132            // smem row stride (floats) to kill bank conflicts
#define SCAN_B 1024

// ---------------- scratch (device globals; no allocation allowed) ------------
__device__ float g_Whp  [(size_t)NP*HD];
__device__ float g_Wha  [(size_t)NP*HD];
__device__ float g_Whp2p[(size_t)NP*HD];
__device__ float g_Whp2a[(size_t)NP*HD];
__device__ float g_Wha2p[(size_t)NP*HD];
__device__ float g_Wha2a[(size_t)NP*HD];
__device__ float g_es[4*(size_t)NP*NH];   // per-relation src-node attn dots
__device__ float g_ed[4*(size_t)NP*NH];   // per-relation dst-node attn dots
__device__ int   g_deg   [4*NP];          // per-(relation,dst) in-degree
__device__ int   g_rowptr[4*NP];          // exclusive scan of g_deg
__device__ int   g_cursor[4*NP];          // scatter cursors (init = rowptr)
__device__ int   g_csrsrc[4*EDGES];       // src ids grouped by (relation,dst)
__device__ int   g_bsum  [512];           // block sums for the scan

// ---------------- helpers ----------------------------------------------------
__device__ __forceinline__ float leaky(float x) {
    return x > 0.f ? x : 0.2f * x;
}

__device__ __forceinline__ unsigned f2tf32(float f) {
    unsigned u;
    asm("cvt.rna.tf32.f32 %0, %1;" : "=r"(u) : "f"(f));
    return u;
}

__device__ __forceinline__ void mma_tf32(float d[4], const unsigned a[4],
                                         unsigned b0, unsigned b1) {
    asm volatile(
        "mma.sync.aligned.m16n8k8.row.col.f32.tf32.tf32.f32 "
        "{%0,%1,%2,%3}, {%4,%5,%6,%7}, {%8,%9}, {%0,%1,%2,%3};"
        : "+f"(d[0]), "+f"(d[1]), "+f"(d[2]), "+f"(d[3])
        : "r"(a[0]), "r"(a[1]), "r"(a[2]), "r"(a[3]), "r"(b0), "r"(b1));
}

// ---------------- 6-in-1 tensor-core GEMM (blockIdx.y = job) -----------------
// Per-block body identical to the measured 47.6us/launch kernel; fusing the 6
// launches into one removes 6x launch tails (2.64 waves each -> 15.9 waves
// total) and keeps X_P/X_A (102MB) L2-resident across jobs.
struct Job {
    const float *X, *W, *Bv, *att1, *att2;
    float *Wh, *acc2, *o1, *o2;
};
struct Jobs6 { Job j[6]; };

__global__ void __launch_bounds__(256, 2)
gemm_tc6(int M, Jobs6 jobs)
{
    extern __shared__ float sm[];
    float* As = sm;               // 128 x PAD (tf32 bit patterns), full K=128
    float* Ws = sm + 128 * PAD;   // 64 x PAD, one K-chunk of W
    const int tid  = threadIdx.x;
    const int row0 = blockIdx.x * 128;

    const Job jb = jobs.j[blockIdx.y];
    const float* __restrict__ X    = jb.X;
    const float* __restrict__ W    = jb.W;
    const float* __restrict__ Bv   = jb.Bv;
    const float* __restrict__ att1 = jb.att1;
    const float* __restrict__ att2 = jb.att2;
    float* __restrict__ Wh   = jb.Wh;
    float* __restrict__ acc2 = jb.acc2;
    float* __restrict__ o1   = jb.o1;
    float* __restrict__ o2   = jb.o2;

    // load X tile [128][128] -> tf32, zero-pad past M (4096 float4)
    #pragma unroll
    for (int i = 0; i < 16; i++) {
        int idx = tid + i * 256;
        int r = idx >> 5, c4 = idx & 31;
        int gr = row0 + r;
        float4 v = (gr < M) ? ((const float4*)X)[(size_t)gr * 32 + c4]
                            : make_float4(0.f, 0.f, 0.f, 0.f);
        float* d = As + r * PAD + c4 * 4;
        ((unsigned*)d)[0] = f2tf32(v.x);
        ((unsigned*)d)[1] = f2tf32(v.y);
        ((unsigned*)d)[2] = f2tf32(v.z);
        ((unsigned*)d)[3] = f2tf32(v.w);
    }

    const int wid   = tid >> 5;
    const int lane  = tid & 31;
    const int warpM = wid & 3;
    const int warpN = wid >> 2;
    const int wm    = warpM * 32;
    const int wn    = warpN * 64;
    const int g     = lane >> 2;
    const int tig   = lane & 3;

    const unsigned* Au = (const unsigned*)As;
    const unsigned* Wu = (const unsigned*)Ws;

    float acc[2][8][4];
    #pragma unroll
    for (int mi = 0; mi < 2; mi++)
        #pragma unroll
        for (int ni = 0; ni < 8; ni++)
            #pragma unroll
            for (int q = 0; q < 4; q++) acc[mi][ni][q] = 0.f;

    #pragma unroll
    for (int kh = 0; kh < 2; kh++) {
        __syncthreads();
        #pragma unroll
        for (int i = 0; i < 8; i++) {
            int idx = tid + i * 256;
            int r = idx >> 5, c4 = idx & 31;
            float4 v = ((const float4*)W)[idx + kh * 2048];
            float* d = Ws + r * PAD + c4 * 4;
            ((unsigned*)d)[0] = f2tf32(v.x);
            ((unsigned*)d)[1] = f2tf32(v.y);
            ((unsigned*)d)[2] = f2tf32(v.z);
            ((unsigned*)d)[3] = f2tf32(v.w);
        }
        __syncthreads();

        #pragma unroll
        for (int kkk = 0; kkk < 8; kkk++) {
            const int k0  = kh * 64 + kkk * 8;
            const int k0l = kkk * 8;
            unsigned a[2][4];
            #pragma unroll
            for (int mi = 0; mi < 2; mi++) {
                int rb = wm + mi * 16;
                a[mi][0] = Au[(rb + g    ) * PAD + k0 + tig];
                a[mi][1] = Au[(rb + g + 8) * PAD + k0 + tig];
                a[mi][2] = Au[(rb + g    ) * PAD + k0 + tig + 4];
                a[mi][3] = Au[(rb + g + 8) * PAD + k0 + tig + 4];
            }
            #pragma unroll
            for (int ni = 0; ni < 8; ni++) {
                unsigned b0 = Wu[(k0l + tig    ) * PAD + wn + ni * 8 + g];
                unsigned b1 = Wu[(k0l + tig + 4) * PAD + wn + ni * 8 + g];
                mma_tf32(acc[0][ni], a[0], b0, b1);
                mma_tf32(acc[1][ni], a[1], b0, b1);
            }
        }
    }

    float pa[2][2][2][2];
    #pragma unroll
    for (int v = 0; v < 2; v++)
        #pragma unroll
        for (int mi = 0; mi < 2; mi++)
            #pragma unroll
            for (int hf = 0; hf < 2; hf++)
                #pragma unroll
                for (int hl = 0; hl < 2; hl++) pa[v][mi][hf][hl] = 0.f;

    #pragma unroll
    for (int ni = 0; ni < 8; ni++) {
        const int c0 = wn + ni * 8 + 2 * tig;
        const int hl = ni >> 2;
        const float b0 = __ldg(Bv + c0), b1 = __ldg(Bv + c0 + 1);
        float a10 = 0.f, a11 = 0.f, a20 = 0.f, a21 = 0.f;
        if (att1) { a10 = __ldg(att1 + c0); a11 = __ldg(att1 + c0 + 1); }
        if (att2) { a20 = __ldg(att2 + c0); a21 = __ldg(att2 + c0 + 1); }
        #pragma unroll
        for (int mi = 0; mi < 2; mi++) {
            int r0 = row0 + wm + mi * 16 + g;
            float y00 = acc[mi][ni][0] + b0, y01 = acc[mi][ni][1] + b1;
            float y10 = acc[mi][ni][2] + b0, y11 = acc[mi][ni][3] + b1;
            if (r0 < M) {
                *(float2*)(Wh + (size_t)r0 * HD + c0) = make_float2(y00, y01);
                if (acc2) *(float2*)(acc2 + (size_t)r0 * HD + c0) = make_float2(y00, y01);
            }
            if (r0 + 8 < M) {
                *(float2*)(Wh + (size_t)(r0 + 8) * HD + c0) = make_float2(y10, y11);
                if (acc2) *(float2*)(acc2 + (size_t)(r0 + 8) * HD + c0) = make_float2(y10, y11);
            }
            pa[0][mi][0][hl] += y00 * a10 + y01 * a11;
            pa[0][mi][1][hl] += y10 * a10 + y11 * a11;
            pa[1][mi][0][hl] += y00 * a20 + y01 * a21;
            pa[1][mi][1][hl] += y10 * a20 + y11 * a21;
        }
    }

    #pragma unroll
    for (int v = 0; v < 2; v++) {
        float* o = (v == 0) ? o1 : o2;
        if (!o) continue;
        #pragma unroll
        for (int mi = 0; mi < 2; mi++)
            #pragma unroll
            for (int hf = 0; hf < 2; hf++)
                #pragma unroll
                for (int hl = 0; hl < 2; hl++) {
                    float p = pa[v][mi][hf][hl];
                    p += __shfl_down_sync(0xffffffffu, p, 2, 4);
                    p += __shfl_down_sync(0xffffffffu, p, 1, 4);
                    if (tig == 0) {
                        int r = row0 + wm + mi * 16 + hf * 8 + g;
                        if (r < M) o[(size_t)r * NH + warpN * 2 + hl] = p;
                    }
                }
    }
}

// ---------------- CSR construction (all 4 relations concatenated) ------------
struct RelPtrs {
    const int* src[4];
    const int* dst[4];
};

__global__ void zero_deg() {
    int i = blockIdx.x * blockDim.x + threadIdx.x;
    if (i < 4 * NP) g_deg[i] = 0;
}

__global__ void count_deg(RelPtrs rp) {
    int i = blockIdx.x * blockDim.x + threadIdx.x;
    if (i >= 4 * EDGES) return;
    int r = i / EDGES;
    int e = i - r * EDGES;
    atomicAdd(&g_deg[r * NP + rp.dst[r][e]], 1);
}

__global__ void scan_p1(int n) {
    __shared__ int wtot[32];
    int i = blockIdx.x * SCAN_B + threadIdx.x;
    int v = (i < n) ? g_deg[i] : 0;
    #pragma unroll
    for (int o = 16; o; o >>= 1) v += __shfl_down_sync(0xffffffffu, v, o);
    if ((threadIdx.x & 31) == 0) wtot[threadIdx.x >> 5] = v;
    __syncthreads();
    if (threadIdx.x < 32) {
        int w = wtot[threadIdx.x];
        #pragma unroll
        for (int o = 16; o; o >>= 1) w += __shfl_down_sync(0xffffffffu, w, o);
        if (threadIdx.x == 0) g_bsum[blockIdx.x] = w;
    }
}

__global__ void scan_p2(int nb) {
    __shared__ int wtot[16];
    int tid = threadIdx.x;
    int lane = tid & 31, wid = tid >> 5;
    int v = (tid < nb) ? g_bsum[tid] : 0;
    int inc = v;
    #pragma unroll
    for (int o = 1; o < 32; o <<= 1) {
        int t = __shfl_up_sync(0xffffffffu, inc, o);
        if (lane >= o) inc += t;
    }
    if (lane == 31) wtot[wid] = inc;
    __syncthreads();
    if (tid < 16) {
        int w = wtot[tid];
        int winc = w;
        #pragma unroll
        for (int o = 1; o < 16; o <<= 1) {
            int t = __shfl_up_sync(0x0000ffffu, winc, o);
            if (tid >= o) winc += t;
        }
        wtot[tid] = winc - w;
    }
    __syncthreads();
    if (tid < nb) g_bsum[tid] = inc - v + wtot[wid];
}

__global__ void scan_p3(int n) {
    __shared__ int wtot[32];
    int i = blockIdx.x * SCAN_B + threadIdx.x;
    int lane = threadIdx.x & 31, wid = threadIdx.x >> 5;
    int v = (i < n) ? g_deg[i] : 0;
    int inc = v;
    #pragma unroll
    for (int o = 1; o < 32; o <<= 1) {
        int t = __shfl_up_sync(0xffffffffu, inc, o);
        if (lane >= o) inc += t;
    }
    if (lane == 31) wtot[wid] = inc;
    __syncthreads();
    if (threadIdx.x < 32) {
        int w = wtot[threadIdx.x];
        int winc = w;
        #pragma unroll
        for (int o = 1; o < 32; o <<= 1) {
            int t = __shfl_up_sync(0xffffffffu, winc, o);
            if (threadIdx.x >= o) winc += t;
        }
        wtot[threadIdx.x] = winc - w;
    }
    __syncthreads();
    if (i < n) {
        int ex = inc - v + wtot[wid] + g_bsum[blockIdx.x];
        g_rowptr[i] = ex;
        g_cursor[i] = ex;
    }
}

__global__ void csr_scatter(RelPtrs rp) {
    int i = blockIdx.x * blockDim.x + threadIdx.x;
    if (i >= 4 * EDGES) return;
    int r = i / EDGES;
    int e = i - r * EDGES;
    int d = rp.dst[r][e];
    int pos = atomicAdd(&g_cursor[r * NP + d], 1);
    g_csrsrc[pos] = rp.src[r][e];
}

// ---------------- CSR aggregation v2: warp-prefetch, optional fused ReLU -----
// One warp per dst. Lanes co-load up to 32 src ids (coalesced) + each src's es
// float4 (MLP=32 gather); the accumulation loop gets both via shfl so the only
// in-loop memory op is the Wh gather. do_relu=1 on the LAST launch per output
// half applies ReLU in place (deg==0 rows included).
__global__ void edge_agg(const int* __restrict__ rowptr, const int* __restrict__ deg,
                         const float* __restrict__ es, const float* __restrict__ ed,
                         const float* __restrict__ Wh, float* __restrict__ out,
                         int do_relu)
{
    int gt = blockIdx.x * blockDim.x + threadIdx.x;
    int d = gt >> 5;
    if (d >= NP) return;
    int lane = gt & 31;
    int h = lane >> 3;
    int cnt = deg[d];
    float* op = out + (size_t)d * HD + lane * 4;
    if (cnt == 0) {
        if (do_relu) {
            float4 o = *(float4*)op;
            o.x = fmaxf(o.x, 0.f); o.y = fmaxf(o.y, 0.f);
            o.z = fmaxf(o.z, 0.f); o.w = fmaxf(o.w, 0.f);
            *(float4*)op = o;
        }
        return;
    }
    int beg = rowptr[d];
    float edh = ed[(size_t)d * NH + h];
    float ssum = 0.f, ax = 0.f, ay = 0.f, az = 0.f, aw = 0.f;
    for (int base = 0; base < cnt; base += 32) {
        int rem = cnt - base;
        int n = rem < 32 ? rem : 32;
        int sl = 0;
        float4 e4 = make_float4(0.f, 0.f, 0.f, 0.f);
        if (lane < n) {
            sl = g_csrsrc[beg + base + lane];
            e4 = *(const float4*)(es + (size_t)sl * NH);
        }
        for (int e = 0; e < n; e++) {
            int   s  = __shfl_sync(0xffffffffu, sl,  e);
            float x0 = __shfl_sync(0xffffffffu, e4.x, e);
            float x1 = __shfl_sync(0xffffffffu, e4.y, e);
            float x2 = __shfl_sync(0xffffffffu, e4.z, e);
            float x3 = __shfl_sync(0xffffffffu, e4.w, e);
            float esh = (h == 0) ? x0 : (h == 1) ? x1 : (h == 2) ? x2 : x3;
            float eh = __expf(leaky(esh + edh));
            float4 v = *(const float4*)(Wh + (size_t)s * HD + lane * 4);
            ssum += eh;
            ax += eh * v.x; ay += eh * v.y; az += eh * v.z; aw += eh * v.w;
        }
    }
    float inv = __frcp_rn(ssum);
    float4 o = *(float4*)op;
    o.x += ax * inv; o.y += ay * inv; o.z += az * inv; o.w += aw * inv;
    if (do_relu) {
        o.x = fmaxf(o.x, 0.f); o.y = fmaxf(o.y, 0.f);
        o.z = fmaxf(o.z, 0.f); o.w = fmaxf(o.w, 0.f);
    }
    *(float4*)op = o;
}

// -----------------------------------------------------------------------------
extern "C" void kernel_launch(void* const* d_in, const int* in_sizes, int n_in,
                              void* d_out, int out_size)
{
    const float* feat_P = (const float*)d_in[0];
    const float* feat_A = (const float*)d_in[1];
    const int* src[4] = { (const int*)d_in[2], (const int*)d_in[4],
                          (const int*)d_in[6], (const int*)d_in[8] };
    const int* dst[4] = { (const int*)d_in[3], (const int*)d_in[5],
                          (const int*)d_in[7], (const int*)d_in[9] };
    const float* W_P   = (const float*)d_in[10]; const float* b_P   = (const float*)d_in[11];
    const float* W_A   = (const float*)d_in[12]; const float* b_A   = (const float*)d_in[13];
    const float* W_p2p = (const float*)d_in[14]; const float* b_p2p = (const float*)d_in[15];
    const float* W_p2a = (const float*)d_in[16]; const float* b_p2a = (const float*)d_in[17];
    const float* W_a2p = (const float*)d_in[18]; const float* b_a2p = (const float*)d_in[19];
    const float* W_a2a = (const float*)d_in[20]; const float* b_a2a = (const float*)d_in[21];
    const float* att_src[4] = { (const float*)d_in[22], (const float*)d_in[24],
                                (const float*)d_in[26], (const float*)d_in[28] };
    const float* att_dst[4] = { (const float*)d_in[23], (const float*)d_in[25],
                                (const float*)d_in[27], (const float*)d_in[29] };

    float* out  = (float*)d_out;
    float* outP = out;
    float* outA = out + (size_t)NP * HD;

    float *whp, *wha, *whp2p, *whp2a, *wha2p, *wha2a, *esb, *edb;
    int *degp, *rowp;
    cudaGetSymbolAddress((void**)&whp,   g_Whp);
    cudaGetSymbolAddress((void**)&wha,   g_Wha);
    cudaGetSymbolAddress((void**)&whp2p, g_Whp2p);
    cudaGetSymbolAddress((void**)&whp2a, g_Whp2a);
    cudaGetSymbolAddress((void**)&wha2p, g_Wha2p);
    cudaGetSymbolAddress((void**)&wha2a, g_Wha2a);
    cudaGetSymbolAddress((void**)&esb,   g_es);
    cudaGetSymbolAddress((void**)&edb,   g_ed);
    cudaGetSymbolAddress((void**)&degp,  g_deg);
    cudaGetSymbolAddress((void**)&rowp,  g_rowptr);

    const size_t SMEM = (128 + 64) * PAD * sizeof(float);   // 101376
    cudaFuncSetAttribute(gemm_tc6, cudaFuncAttributeMaxDynamicSharedMemorySize, (int)SMEM);

    RelPtrs rp;
    for (int r = 0; r < 4; r++) { rp.src[r] = src[r]; rp.dst[r] = dst[r]; }

    // ---- CSR build (independent of GEMMs) ----
    const int N4  = 4 * NP;
    const int NB1 = (N4 + SCAN_B - 1) / SCAN_B;   // 391
    zero_deg<<<(N4 + 255) / 256, 256>>>();
    count_deg<<<(4 * EDGES + 255) / 256, 256>>>(rp);
    scan_p1<<<NB1, SCAN_B>>>(N4);
    scan_p2<<<1, 512>>>(NB1);
    scan_p3<<<NB1, SCAN_B>>>(N4);
    csr_scatter<<<(4 * EDGES + 255) / 256, 256>>>(rp);

    // ---- dense phase: all 6 GEMMs in one launch (blockIdx.y = job) ----
    const int GB = (NP + 127) / 128;
    const size_t T = (size_t)NP * NH;

    Jobs6 js;
    js.j[0] = { feat_P, W_P,   b_P,   att_dst[0], att_dst[2], whp,   outP,    edb + 0 * T, edb + 2 * T };
    js.j[1] = { feat_A, W_A,   b_A,   att_dst[1], att_dst[3], wha,   outA,    edb + 1 * T, edb + 3 * T };
    js.j[2] = { feat_P, W_p2p, b_p2p, att_src[0], nullptr,    whp2p, nullptr, esb + 0 * T, nullptr     };
    js.j[3] = { feat_P, W_p2a, b_p2a, att_src[1], nullptr,    whp2a, nullptr, esb + 1 * T, nullptr     };
    js.j[4] = { feat_A, W_a2p, b_a2p, att_src[2], nullptr,    wha2p, nullptr, esb + 2 * T, nullptr     };
    js.j[5] = { feat_A, W_a2a, b_a2a, att_src[3], nullptr,    wha2a, nullptr, esb + 3 * T, nullptr     };
    gemm_tc6<<<dim3(GB, 6), 256, SMEM>>>(NP, js);

    // ---- edge aggregation: atomic-free, per-relation; ReLU fused into the
    //      last launch targeting each output half ----
    edge_agg<<<(int)(((size_t)NP * 32 + 255) / 256), 256>>>(
        rowp + 0 * NP, degp + 0 * NP, esb + 0 * T, edb + 0 * T, whp2p, outP, 0);
    edge_agg<<<(int)(((size_t)NP * 32 + 255) / 256), 256>>>(
        rowp + 2 * NP, degp + 2 * NP, esb + 2 * T, edb + 2 * T, wha2p, outP, 1);
    edge_agg<<<(int)(((size_t)NP * 32 + 255) / 256), 256>>>(
        rowp + 1 * NP, degp + 1 * NP, esb + 1 * T, edb + 1 * T, whp2a, outA, 0);
    edge_agg<<<(int)(((size_t)NP * 32 + 255) / 256), 256>>>(
        rowp + 3 * NP, degp + 3 * NP, esb + 3 * T, edb + 3 * T, wha2a, outA, 1);
}

// round 15
// speedup vs baseline: 1.1713x; 1.1713x over previous
#include <cuda_runtime.h>
#include <math_constants.h>

#define NP 100000          // nodes per type (N_P == N_A)
#define EDGES 500000
#define HD 128             // H*D
#define NH 4               // heads
#define PAD 132            // smem row stride (floats) to kill bank conflicts
#define SCAN_B 1024

// ---------------- scratch (device globals; no allocation allowed) ------------
__device__ float g_Whp2p[(size_t)NP*HD];
__device__ float g_Whp2a[(size_t)NP*HD];
__device__ float g_Wha2p[(size_t)NP*HD];
__device__ float g_Wha2a[(size_t)NP*HD];
__device__ float g_es[4*(size_t)NP*NH];   // per-relation src-node attn dots
__device__ float g_ed[4*(size_t)NP*NH];   // per-relation dst-node attn dots
__device__ int   g_deg   [4*NP];          // per-(relation,dst) in-degree
__device__ int   g_rowptr[4*NP];          // exclusive scan of g_deg
__device__ int   g_cursor[4*NP];          // scatter cursors (init = rowptr)
__device__ int   g_csrsrc[4*EDGES];       // src ids grouped by (relation,dst)
__device__ int   g_bsum  [512];           // block sums for the scan

// ---------------- helpers ----------------------------------------------------
__device__ __forceinline__ float leaky(float x) {
    return x > 0.f ? x : 0.2f * x;
}

__device__ __forceinline__ unsigned f2tf32(float f) {
    unsigned u;
    asm("cvt.rna.tf32.f32 %0, %1;" : "=r"(u) : "f"(f));
    return u;
}

__device__ __forceinline__ void mma_tf32(float d[4], const unsigned a[4],
                                         unsigned b0, unsigned b1) {
    asm volatile(
        "mma.sync.aligned.m16n8k8.row.col.f32.tf32.tf32.f32 "
        "{%0,%1,%2,%3}, {%4,%5,%6,%7}, {%8,%9}, {%0,%1,%2,%3};"
        : "+f"(d[0]), "+f"(d[1]), "+f"(d[2]), "+f"(d[3])
        : "r"(a[0]), "r"(a[1]), "r"(a[2]), "r"(a[3]), "r"(b0), "r"(b1));
}

// ---------------- tensor-core GEMM: Wh = X@W + b, fused attn-dot epilogue ----
// Measured 47.6us/launch (2 blocks/SM via K-chunked W). For the two self
// transforms, Wh points straight at d_out and acc2 is null (the old duplicate
// 51MB store to a scratch Wh was write-only -> removed).
__global__ void __launch_bounds__(256, 2)
gemm_tc(const float* __restrict__ X, const float* __restrict__ W,
        const float* __restrict__ Bv, int M,
        float* __restrict__ Wh, float* __restrict__ acc2,
        const float* __restrict__ att1, float* __restrict__ o1,
        const float* __restrict__ att2, float* __restrict__ o2)
{
    extern __shared__ float sm[];
    float* As = sm;               // 128 x PAD (tf32 bit patterns), full K=128
    float* Ws = sm + 128 * PAD;   // 64 x PAD, one K-chunk of W
    const int tid  = threadIdx.x;
    const int row0 = blockIdx.x * 128;

    // load X tile [128][128] -> tf32, zero-pad past M (4096 float4)
    #pragma unroll
    for (int i = 0; i < 16; i++) {
        int idx = tid + i * 256;
        int r = idx >> 5, c4 = idx & 31;
        int gr = row0 + r;
        float4 v = (gr < M) ? ((const float4*)X)[(size_t)gr * 32 + c4]
                            : make_float4(0.f, 0.f, 0.f, 0.f);
        float* d = As + r * PAD + c4 * 4;
        ((unsigned*)d)[0] = f2tf32(v.x);
        ((unsigned*)d)[1] = f2tf32(v.y);
        ((unsigned*)d)[2] = f2tf32(v.z);
        ((unsigned*)d)[3] = f2tf32(v.w);
    }

    const int wid   = tid >> 5;
    const int lane  = tid & 31;
    const int warpM = wid & 3;
    const int warpN = wid >> 2;
    const int wm    = warpM * 32;
    const int wn    = warpN * 64;
    const int g     = lane >> 2;
    const int tig   = lane & 3;

    const unsigned* Au = (const unsigned*)As;
    const unsigned* Wu = (const unsigned*)Ws;

    float acc[2][8][4];
    #pragma unroll
    for (int mi = 0; mi < 2; mi++)
        #pragma unroll
        for (int ni = 0; ni < 8; ni++)
            #pragma unroll
            for (int q = 0; q < 4; q++) acc[mi][ni][q] = 0.f;

    #pragma unroll
    for (int kh = 0; kh < 2; kh++) {
        __syncthreads();
        #pragma unroll
        for (int i = 0; i < 8; i++) {
            int idx = tid + i * 256;
            int r = idx >> 5, c4 = idx & 31;
            float4 v = ((const float4*)W)[idx + kh * 2048];
            float* d = Ws + r * PAD + c4 * 4;
            ((unsigned*)d)[0] = f2tf32(v.x);
            ((unsigned*)d)[1] = f2tf32(v.y);
            ((unsigned*)d)[2] = f2tf32(v.z);
            ((unsigned*)d)[3] = f2tf32(v.w);
        }
        __syncthreads();

        #pragma unroll
        for (int kkk = 0; kkk < 8; kkk++) {
            const int k0  = kh * 64 + kkk * 8;
            const int k0l = kkk * 8;
            unsigned a[2][4];
            #pragma unroll
            for (int mi = 0; mi < 2; mi++) {
                int rb = wm + mi * 16;
                a[mi][0] = Au[(rb + g    ) * PAD + k0 + tig];
                a[mi][1] = Au[(rb + g + 8) * PAD + k0 + tig];
                a[mi][2] = Au[(rb + g    ) * PAD + k0 + tig + 4];
                a[mi][3] = Au[(rb + g + 8) * PAD + k0 + tig + 4];
            }
            #pragma unroll
            for (int ni = 0; ni < 8; ni++) {
                unsigned b0 = Wu[(k0l + tig    ) * PAD + wn + ni * 8 + g];
                unsigned b1 = Wu[(k0l + tig + 4) * PAD + wn + ni * 8 + g];
                mma_tf32(acc[0][ni], a[0], b0, b1);
                mma_tf32(acc[1][ni], a[1], b0, b1);
            }
        }
    }

    float pa[2][2][2][2];
    #pragma unroll
    for (int v = 0; v < 2; v++)
        #pragma unroll
        for (int mi = 0; mi < 2; mi++)
            #pragma unroll
            for (int hf = 0; hf < 2; hf++)
                #pragma unroll
                for (int hl = 0; hl < 2; hl++) pa[v][mi][hf][hl] = 0.f;

    #pragma unroll
    for (int ni = 0; ni < 8; ni++) {
        const int c0 = wn + ni * 8 + 2 * tig;
        const int hl = ni >> 2;
        const float b0 = __ldg(Bv + c0), b1 = __ldg(Bv + c0 + 1);
        float a10 = 0.f, a11 = 0.f, a20 = 0.f, a21 = 0.f;
        if (att1) { a10 = __ldg(att1 + c0); a11 = __ldg(att1 + c0 + 1); }
        if (att2) { a20 = __ldg(att2 + c0); a21 = __ldg(att2 + c0 + 1); }
        #pragma unroll
        for (int mi = 0; mi < 2; mi++) {
            int r0 = row0 + wm + mi * 16 + g;
            float y00 = acc[mi][ni][0] + b0, y01 = acc[mi][ni][1] + b1;
            float y10 = acc[mi][ni][2] + b0, y11 = acc[mi][ni][3] + b1;
            if (r0 < M) {
                *(float2*)(Wh + (size_t)r0 * HD + c0) = make_float2(y00, y01);
                if (acc2) *(float2*)(acc2 + (size_t)r0 * HD + c0) = make_float2(y00, y01);
            }
            if (r0 + 8 < M) {
                *(float2*)(Wh + (size_t)(r0 + 8) * HD + c0) = make_float2(y10, y11);
                if (acc2) *(float2*)(acc2 + (size_t)(r0 + 8) * HD + c0) = make_float2(y10, y11);
            }
            pa[0][mi][0][hl] += y00 * a10 + y01 * a11;
            pa[0][mi][1][hl] += y10 * a10 + y11 * a11;
            pa[1][mi][0][hl] += y00 * a20 + y01 * a21;
            pa[1][mi][1][hl] += y10 * a20 + y11 * a21;
        }
    }

    #pragma unroll
    for (int v = 0; v < 2; v++) {
        float* o = (v == 0) ? o1 : o2;
        if (!o) continue;
        #pragma unroll
        for (int mi = 0; mi < 2; mi++)
            #pragma unroll
            for (int hf = 0; hf < 2; hf++)
                #pragma unroll
                for (int hl = 0; hl < 2; hl++) {
                    float p = pa[v][mi][hf][hl];
                    p += __shfl_down_sync(0xffffffffu, p, 2, 4);
                    p += __shfl_down_sync(0xffffffffu, p, 1, 4);
                    if (tig == 0) {
                        int r = row0 + wm + mi * 16 + hf * 8 + g;
                        if (r < M) o[(size_t)r * NH + warpN * 2 + hl] = p;
                    }
                }
    }
}

// ---------------- CSR construction (all 4 relations concatenated) ------------
struct RelPtrs {
    const int* src[4];
    const int* dst[4];
};

__global__ void zero_deg() {
    int i = blockIdx.x * blockDim.x + threadIdx.x;
    if (i < 4 * NP) g_deg[i] = 0;
}

__global__ void count_deg(RelPtrs rp) {
    int i = blockIdx.x * blockDim.x + threadIdx.x;
    if (i >= 4 * EDGES) return;
    int r = i / EDGES;
    int e = i - r * EDGES;
    atomicAdd(&g_deg[r * NP + rp.dst[r][e]], 1);
}

__global__ void scan_p1(int n) {
    __shared__ int wtot[32];
    int i = blockIdx.x * SCAN_B + threadIdx.x;
    int v = (i < n) ? g_deg[i] : 0;
    #pragma unroll
    for (int o = 16; o; o >>= 1) v += __shfl_down_sync(0xffffffffu, v, o);
    if ((threadIdx.x & 31) == 0) wtot[threadIdx.x >> 5] = v;
    __syncthreads();
    if (threadIdx.x < 32) {
        int w = wtot[threadIdx.x];
        #pragma unroll
        for (int o = 16; o; o >>= 1) w += __shfl_down_sync(0xffffffffu, w, o);
        if (threadIdx.x == 0) g_bsum[blockIdx.x] = w;
    }
}

__global__ void scan_p2(int nb) {
    __shared__ int wtot[16];
    int tid = threadIdx.x;
    int lane = tid & 31, wid = tid >> 5;
    int v = (tid < nb) ? g_bsum[tid] : 0;
    int inc = v;
    #pragma unroll
    for (int o = 1; o < 32; o <<= 1) {
        int t = __shfl_up_sync(0xffffffffu, inc, o);
        if (lane >= o) inc += t;
    }
    if (lane == 31) wtot[wid] = inc;
    __syncthreads();
    if (tid < 16) {
        int w = wtot[tid];
        int winc = w;
        #pragma unroll
        for (int o = 1; o < 16; o <<= 1) {
            int t = __shfl_up_sync(0x0000ffffu, winc, o);
            if (tid >= o) winc += t;
        }
        wtot[tid] = winc - w;
    }
    __syncthreads();
    if (tid < nb) g_bsum[tid] = inc - v + wtot[wid];
}

__global__ void scan_p3(int n) {
    __shared__ int wtot[32];
    int i = blockIdx.x * SCAN_B + threadIdx.x;
    int lane = threadIdx.x & 31, wid = threadIdx.x >> 5;
    int v = (i < n) ? g_deg[i] : 0;
    int inc = v;
    #pragma unroll
    for (int o = 1; o < 32; o <<= 1) {
        int t = __shfl_up_sync(0xffffffffu, inc, o);
        if (lane >= o) inc += t;
    }
    if (lane == 31) wtot[wid] = inc;
    __syncthreads();
    if (threadIdx.x < 32) {
        int w = wtot[threadIdx.x];
        int winc = w;
        #pragma unroll
        for (int o = 1; o < 32; o <<= 1) {
            int t = __shfl_up_sync(0xffffffffu, winc, o);
            if (threadIdx.x >= o) winc += t;
        }
        wtot[threadIdx.x] = winc - w;
    }
    __syncthreads();
    if (i < n) {
        int ex = inc - v + wtot[wid] + g_bsum[blockIdx.x];
        g_rowptr[i] = ex;
        g_cursor[i] = ex;
    }
}

__global__ void csr_scatter(RelPtrs rp) {
    int i = blockIdx.x * blockDim.x + threadIdx.x;
    if (i >= 4 * EDGES) return;
    int r = i / EDGES;
    int e = i - r * EDGES;
    int d = rp.dst[r][e];
    int pos = atomicAdd(&g_cursor[r * NP + d], 1);
    g_csrsrc[pos] = rp.src[r][e];
}

// ---------------- CSR aggregation v1 + fused ReLU ----------------------------
// One warp per dst node (serial per-edge loop, measured as part of 611.9us).
// acc = sum(ee*Wh[src]); out += acc / sum(ee). exp shift skipped (logits O(5),
// softmax shift-invariant). do_relu=1 on the LAST launch per output half
// applies ReLU in place (deg==0 rows included).
__global__ void edge_agg(const int* __restrict__ rowptr, const int* __restrict__ deg,
                         const float* __restrict__ es, const float* __restrict__ ed,
                         const float* __restrict__ Wh, float* __restrict__ out,
                         int do_relu)
{
    int gt = blockIdx.x * blockDim.x + threadIdx.x;
    int d = gt >> 5;
    if (d >= NP) return;
    int lane = gt & 31;
    int h = lane >> 3;
    int cnt = deg[d];
    float* op = out + (size_t)d * HD + lane * 4;
    if (cnt == 0) {
        if (do_relu) {
            float4 o = *(float4*)op;
            o.x = fmaxf(o.x, 0.f); o.y = fmaxf(o.y, 0.f);
            o.z = fmaxf(o.z, 0.f); o.w = fmaxf(o.w, 0.f);
            *(float4*)op = o;
        }
        return;
    }
    int beg = rowptr[d];
    float edh = ed[(size_t)d * NH + h];
    float ssum = 0.f;
    float ax = 0.f, ay = 0.f, az = 0.f, aw = 0.f;
    for (int e = beg; e < beg + cnt; e++) {
        int s = g_csrsrc[e];
        float eh = __expf(leaky(es[(size_t)s * NH + h] + edh));
        float4 v = *(const float4*)(Wh + (size_t)s * HD + lane * 4);
        ssum += eh;
        ax += eh * v.x; ay += eh * v.y; az += eh * v.z; aw += eh * v.w;
    }
    float inv = __frcp_rn(ssum);
    float4 o = *(float4*)op;
    o.x += ax * inv; o.y += ay * inv; o.z += az * inv; o.w += aw * inv;
    if (do_relu) {
        o.x = fmaxf(o.x, 0.f); o.y = fmaxf(o.y, 0.f);
        o.z = fmaxf(o.z, 0.f); o.w = fmaxf(o.w, 0.f);
    }
    *(float4*)op = o;
}

// -----------------------------------------------------------------------------
extern "C" void kernel_launch(void* const* d_in, const int* in_sizes, int n_in,
                              void* d_out, int out_size)
{
    const float* feat_P = (const float*)d_in[0];
    const float* feat_A = (const float*)d_in[1];
    const int* src[4] = { (const int*)d_in[2], (const int*)d_in[4],
                          (const int*)d_in[6], (const int*)d_in[8] };
    const int* dst[4] = { (const int*)d_in[3], (const int*)d_in[5],
                          (const int*)d_in[7], (const int*)d_in[9] };
    const float* W_P   = (const float*)d_in[10]; const float* b_P   = (const float*)d_in[11];
    const float* W_A   = (const float*)d_in[12]; const float* b_A   = (const float*)d_in[13];
    const float* W_p2p = (const float*)d_in[14]; const float* b_p2p = (const float*)d_in[15];
    const float* W_p2a = (const float*)d_in[16]; const float* b_p2a = (const float*)d_in[17];
    const float* W_a2p = (const float*)d_in[18]; const float* b_a2p = (const float*)d_in[19];
    const float* W_a2a = (const float*)d_in[20]; const float* b_a2a = (const float*)d_in[21];
    const float* att_src[4] = { (const float*)d_in[22], (const float*)d_in[24],
                                (const float*)d_in[26], (const float*)d_in[28] };
    const float* att_dst[4] = { (const float*)d_in[23], (const float*)d_in[25],
                                (const float*)d_in[27], (const float*)d_in[29] };

    float* out  = (float*)d_out;
    float* outP = out;
    float* outA = out + (size_t)NP * HD;

    float *whp2p, *whp2a, *wha2p, *wha2a, *esb, *edb;
    int *degp, *rowp;
    cudaGetSymbolAddress((void**)&whp2p, g_Whp2p);
    cudaGetSymbolAddress((void**)&whp2a, g_Whp2a);
    cudaGetSymbolAddress((void**)&wha2p, g_Wha2p);
    cudaGetSymbolAddress((void**)&wha2a, g_Wha2a);
    cudaGetSymbolAddress((void**)&esb,   g_es);
    cudaGetSymbolAddress((void**)&edb,   g_ed);
    cudaGetSymbolAddress((void**)&degp,  g_deg);
    cudaGetSymbolAddress((void**)&rowp,  g_rowptr);

    const size_t SMEM = (128 + 64) * PAD * sizeof(float);   // 101376
    cudaFuncSetAttribute(gemm_tc, cudaFuncAttributeMaxDynamicSharedMemorySize, (int)SMEM);

    RelPtrs rp;
    for (int r = 0; r < 4; r++) { rp.src[r] = src[r]; rp.dst[r] = dst[r]; }

    // ---- CSR build (independent of GEMMs) ----
    const int N4  = 4 * NP;
    const int NB1 = (N4 + SCAN_B - 1) / SCAN_B;   // 391
    zero_deg<<<(N4 + 255) / 256, 256>>>();
    count_deg<<<(4 * EDGES + 255) / 256, 256>>>(rp);
    scan_p1<<<NB1, SCAN_B>>>(N4);
    scan_p2<<<1, 512>>>(NB1);
    scan_p3<<<NB1, SCAN_B>>>(N4);
    csr_scatter<<<(4 * EDGES + 255) / 256, 256>>>(rp);

    // ---- dense phase: 6 GEMMs; self transforms write d_out directly ----
    const int GB = (NP + 127) / 128;
    const size_t T = (size_t)NP * NH;

    gemm_tc<<<GB, 256, SMEM>>>(feat_P, W_P, b_P, NP, outP, nullptr,
                               att_dst[0], edb + 0 * T,   // ed_p2p (dst = P)
                               att_dst[2], edb + 2 * T);  // ed_a2p (dst = P)
    gemm_tc<<<GB, 256, SMEM>>>(feat_A, W_A, b_A, NP, outA, nullptr,
                               att_dst[1], edb + 1 * T,   // ed_p2a (dst = A)
                               att_dst[3], edb + 3 * T);  // ed_a2a (dst = A)
    gemm_tc<<<GB, 256, SMEM>>>(feat_P, W_p2p, b_p2p, NP, whp2p, nullptr,
                               att_src[0], esb + 0 * T, nullptr, nullptr);
    gemm_tc<<<GB, 256, SMEM>>>(feat_P, W_p2a, b_p2a, NP, whp2a, nullptr,
                               att_src[1], esb + 1 * T, nullptr, nullptr);
    gemm_tc<<<GB, 256, SMEM>>>(feat_A, W_a2p, b_a2p, NP, wha2p, nullptr,
                               att_src[2], esb + 2 * T, nullptr, nullptr);
    gemm_tc<<<GB, 256, SMEM>>>(feat_A, W_a2a, b_a2a, NP, wha2a, nullptr,
                               att_src[3], esb + 3 * T, nullptr, nullptr);

    // ---- edge aggregation: atomic-free, per-relation; ReLU fused into the
    //      last launch targeting each output half ----
    const int AGG_B = (int)(((size_t)NP * 32 + 255) / 256);
    edge_agg<<<AGG_B, 256>>>(rowp + 0 * NP, degp + 0 * NP,
                             esb + 0 * T, edb + 0 * T, whp2p, outP, 0);
    edge_agg<<<AGG_B, 256>>>(rowp + 2 * NP, degp + 2 * NP,
                             esb + 2 * T, edb + 2 * T, wha2p, outP, 1);
    edge_agg<<<AGG_B, 256>>>(rowp + 1 * NP, degp + 1 * NP,
                             esb + 1 * T, edb + 1 * T, whp2a, outA, 0);
    edge_agg<<<AGG_B, 256>>>(rowp + 3 * NP, degp + 3 * NP,
                             esb + 3 * T, edb + 3 * T, wha2a, outA, 1);
}

// round 16
// speedup vs baseline: 1.2546x; 1.0711x over previous
#include <cuda_runtime.h>
#include <math_constants.h>

#define NP 100000          // nodes per type (N_P == N_A)
#define EDGES 500000
#define HD 128             // H*D
#define NH 4               // heads
#define PAD 132            // smem row stride (floats) to kill bank conflicts
#define SCAN_B 1024

// ---------------- scratch (device globals; no allocation allowed) ------------
__device__ float g_Whp2p[(size_t)NP*HD];
__device__ float g_Whp2a[(size_t)NP*HD];
__device__ float g_Wha2p[(size_t)NP*HD];
__device__ float g_Wha2a[(size_t)NP*HD];
__device__ float g_es[4*(size_t)NP*NH];   // per-relation src-node attn dots
__device__ float g_ed[4*(size_t)NP*NH];   // per-relation dst-node attn dots
__device__ int   g_deg   [4*NP];          // per-(relation,dst) in-degree
__device__ int   g_rowptr[4*NP];          // exclusive scan of g_deg
__device__ int   g_cursor[4*NP];          // scatter cursors (init = rowptr)
__device__ int   g_csrsrc[4*EDGES];       // src ids grouped by (relation,dst)
__device__ int   g_bsum  [512];           // block sums for the scan

// ---------------- helpers ----------------------------------------------------
__device__ __forceinline__ float leaky(float x) {
    return x > 0.f ? x : 0.2f * x;
}

__device__ __forceinline__ unsigned f2tf32(float f) {
    unsigned u;
    asm("cvt.rna.tf32.f32 %0, %1;" : "=r"(u) : "f"(f));
    return u;
}

__device__ __forceinline__ void mma_tf32(float d[4], const unsigned a[4],
                                         unsigned b0, unsigned b1) {
    asm volatile(
        "mma.sync.aligned.m16n8k8.row.col.f32.tf32.tf32.f32 "
        "{%0,%1,%2,%3}, {%4,%5,%6,%7}, {%8,%9}, {%0,%1,%2,%3};"
        : "+f"(d[0]), "+f"(d[1]), "+f"(d[2]), "+f"(d[3])
        : "r"(a[0]), "r"(a[1]), "r"(a[2]), "r"(a[3]), "r"(b0), "r"(b1));
}

// ---------------- 6-in-1 tensor-core GEMM (blockIdx.y = job) -----------------
// Per-block body byte-identical to the kernel measured at 47.6us/launch; one
// job per block (no cross-job register state). Fusing 6 launches into one
// removes 5 launch gaps and 5 partial-wave tails (2.64 waves each -> 15.85
// waves total). Self transforms write d_out directly (acc2 == nullptr).
struct Job {
    const float *X, *W, *Bv, *att1, *att2;
    float *Wh, *acc2, *o1, *o2;
};
struct Jobs6 { Job j[6]; };

__global__ void __launch_bounds__(256, 2)
gemm_tc6(int M, Jobs6 jobs)
{
    extern __shared__ float sm[];
    float* As = sm;               // 128 x PAD (tf32 bit patterns), full K=128
    float* Ws = sm + 128 * PAD;   // 64 x PAD, one K-chunk of W
    const int tid  = threadIdx.x;
    const int row0 = blockIdx.x * 128;

    const Job jb = jobs.j[blockIdx.y];
    const float* __restrict__ X    = jb.X;
    const float* __restrict__ W    = jb.W;
    const float* __restrict__ Bv   = jb.Bv;
    const float* __restrict__ att1 = jb.att1;
    const float* __restrict__ att2 = jb.att2;
    float* __restrict__ Wh   = jb.Wh;
    float* __restrict__ acc2 = jb.acc2;
    float* __restrict__ o1   = jb.o1;
    float* __restrict__ o2   = jb.o2;

    // load X tile [128][128] -> tf32, zero-pad past M (4096 float4)
    #pragma unroll
    for (int i = 0; i < 16; i++) {
        int idx = tid + i * 256;
        int r = idx >> 5, c4 = idx & 31;
        int gr = row0 + r;
        float4 v = (gr < M) ? ((const float4*)X)[(size_t)gr * 32 + c4]
                            : make_float4(0.f, 0.f, 0.f, 0.f);
        float* d = As + r * PAD + c4 * 4;
        ((unsigned*)d)[0] = f2tf32(v.x);
        ((unsigned*)d)[1] = f2tf32(v.y);
        ((unsigned*)d)[2] = f2tf32(v.z);
        ((unsigned*)d)[3] = f2tf32(v.w);
    }

    const int wid   = tid >> 5;
    const int lane  = tid & 31;
    const int warpM = wid & 3;
    const int warpN = wid >> 2;
    const int wm    = warpM * 32;
    const int wn    = warpN * 64;
    const int g     = lane >> 2;
    const int tig   = lane & 3;

    const unsigned* Au = (const unsigned*)As;
    const unsigned* Wu = (const unsigned*)Ws;

    float acc[2][8][4];
    #pragma unroll
    for (int mi = 0; mi < 2; mi++)
        #pragma unroll
        for (int ni = 0; ni < 8; ni++)
            #pragma unroll
            for (int q = 0; q < 4; q++) acc[mi][ni][q] = 0.f;

    #pragma unroll
    for (int kh = 0; kh < 2; kh++) {
        __syncthreads();
        #pragma unroll
        for (int i = 0; i < 8; i++) {
            int idx = tid + i * 256;
            int r = idx >> 5, c4 = idx & 31;
            float4 v = ((const float4*)W)[idx + kh * 2048];
            float* d = Ws + r * PAD + c4 * 4;
            ((unsigned*)d)[0] = f2tf32(v.x);
            ((unsigned*)d)[1] = f2tf32(v.y);
            ((unsigned*)d)[2] = f2tf32(v.z);
            ((unsigned*)d)[3] = f2tf32(v.w);
        }
        __syncthreads();

        #pragma unroll
        for (int kkk = 0; kkk < 8; kkk++) {
            const int k0  = kh * 64 + kkk * 8;
            const int k0l = kkk * 8;
            unsigned a[2][4];
            #pragma unroll
            for (int mi = 0; mi < 2; mi++) {
                int rb = wm + mi * 16;
                a[mi][0] = Au[(rb + g    ) * PAD + k0 + tig];
                a[mi][1] = Au[(rb + g + 8) * PAD + k0 + tig];
                a[mi][2] = Au[(rb + g    ) * PAD + k0 + tig + 4];
                a[mi][3] = Au[(rb + g + 8) * PAD + k0 + tig + 4];
            }
            #pragma unroll
            for (int ni = 0; ni < 8; ni++) {
                unsigned b0 = Wu[(k0l + tig    ) * PAD + wn + ni * 8 + g];
                unsigned b1 = Wu[(k0l + tig + 4) * PAD + wn + ni * 8 + g];
                mma_tf32(acc[0][ni], a[0], b0, b1);
                mma_tf32(acc[1][ni], a[1], b0, b1);
            }
        }
    }

    float pa[2][2][2][2];
    #pragma unroll
    for (int v = 0; v < 2; v++)
        #pragma unroll
        for (int mi = 0; mi < 2; mi++)
            #pragma unroll
            for (int hf = 0; hf < 2; hf++)
                #pragma unroll
                for (int hl = 0; hl < 2; hl++) pa[v][mi][hf][hl] = 0.f;

    #pragma unroll
    for (int ni = 0; ni < 8; ni++) {
        const int c0 = wn + ni * 8 + 2 * tig;
        const int hl = ni >> 2;
        const float b0 = __ldg(Bv + c0), b1 = __ldg(Bv + c0 + 1);
        float a10 = 0.f, a11 = 0.f, a20 = 0.f, a21 = 0.f;
        if (att1) { a10 = __ldg(att1 + c0); a11 = __ldg(att1 + c0 + 1); }
        if (att2) { a20 = __ldg(att2 + c0); a21 = __ldg(att2 + c0 + 1); }
        #pragma unroll
        for (int mi = 0; mi < 2; mi++) {
            int r0 = row0 + wm + mi * 16 + g;
            float y00 = acc[mi][ni][0] + b0, y01 = acc[mi][ni][1] + b1;
            float y10 = acc[mi][ni][2] + b0, y11 = acc[mi][ni][3] + b1;
            if (r0 < M) {
                *(float2*)(Wh + (size_t)r0 * HD + c0) = make_float2(y00, y01);
                if (acc2) *(float2*)(acc2 + (size_t)r0 * HD + c0) = make_float2(y00, y01);
            }
            if (r0 + 8 < M) {
                *(float2*)(Wh + (size_t)(r0 + 8) * HD + c0) = make_float2(y10, y11);
                if (acc2) *(float2*)(acc2 + (size_t)(r0 + 8) * HD + c0) = make_float2(y10, y11);
            }
            pa[0][mi][0][hl] += y00 * a10 + y01 * a11;
            pa[0][mi][1][hl] += y10 * a10 + y11 * a11;
            pa[1][mi][0][hl] += y00 * a20 + y01 * a21;
            pa[1][mi][1][hl] += y10 * a20 + y11 * a21;
        }
    }

    #pragma unroll
    for (int v = 0; v < 2; v++) {
        float* o = (v == 0) ? o1 : o2;
        if (!o) continue;
        #pragma unroll
        for (int mi = 0; mi < 2; mi++)
            #pragma unroll
            for (int hf = 0; hf < 2; hf++)
                #pragma unroll
                for (int hl = 0; hl < 2; hl++) {
                    float p = pa[v][mi][hf][hl];
                    p += __shfl_down_sync(0xffffffffu, p, 2, 4);
                    p += __shfl_down_sync(0xffffffffu, p, 1, 4);
                    if (tig == 0) {
                        int r = row0 + wm + mi * 16 + hf * 8 + g;
                        if (r < M) o[(size_t)r * NH + warpN * 2 + hl] = p;
                    }
                }
    }
}

// ---------------- CSR construction (all 4 relations concatenated) ------------
struct RelPtrs {
    const int* src[4];
    const int* dst[4];
};

__global__ void count_deg(RelPtrs rp) {
    int i = blockIdx.x * blockDim.x + threadIdx.x;
    if (i >= 4 * EDGES) return;
    int r = i / EDGES;
    int e = i - r * EDGES;
    atomicAdd(&g_deg[r * NP + rp.dst[r][e]], 1);
}

__global__ void scan_p1(int n) {
    __shared__ int wtot[32];
    int i = blockIdx.x * SCAN_B + threadIdx.x;
    int v = (i < n) ? g_deg[i] : 0;
    #pragma unroll
    for (int o = 16; o; o >>= 1) v += __shfl_down_sync(0xffffffffu, v, o);
    if ((threadIdx.x & 31) == 0) wtot[threadIdx.x >> 5] = v;
    __syncthreads();
    if (threadIdx.x < 32) {
        int w = wtot[threadIdx.x];
        #pragma unroll
        for (int o = 16; o; o >>= 1) w += __shfl_down_sync(0xffffffffu, w, o);
        if (threadIdx.x == 0) g_bsum[blockIdx.x] = w;
    }
}

__global__ void scan_p2(int nb) {
    __shared__ int wtot[16];
    int tid = threadIdx.x;
    int lane = tid & 31, wid = tid >> 5;
    int v = (tid < nb) ? g_bsum[tid] : 0;
    int inc = v;
    #pragma unroll
    for (int o = 1; o < 32; o <<= 1) {
        int t = __shfl_up_sync(0xffffffffu, inc, o);
        if (lane >= o) inc += t;
    }
    if (lane == 31) wtot[wid] = inc;
    __syncthreads();
    if (tid < 16) {
        int w = wtot[tid];
        int winc = w;
        #pragma unroll
        for (int o = 1; o < 16; o <<= 1) {
            int t = __shfl_up_sync(0x0000ffffu, winc, o);
            if (tid >= o) winc += t;
        }
        wtot[tid] = winc - w;
    }
    __syncthreads();
    if (tid < nb) g_bsum[tid] = inc - v + wtot[wid];
}

__global__ void scan_p3(int n) {
    __shared__ int wtot[32];
    int i = blockIdx.x * SCAN_B + threadIdx.x;
    int lane = threadIdx.x & 31, wid = threadIdx.x >> 5;
    int v = (i < n) ? g_deg[i] : 0;
    int inc = v;
    #pragma unroll
    for (int o = 1; o < 32; o <<= 1) {
        int t = __shfl_up_sync(0xffffffffu, inc, o);
        if (lane >= o) inc += t;
    }
    if (lane == 31) wtot[wid] = inc;
    __syncthreads();
    if (threadIdx.x < 32) {
        int w = wtot[threadIdx.x];
        int winc = w;
        #pragma unroll
        for (int o = 1; o < 32; o <<= 1) {
            int t = __shfl_up_sync(0xffffffffu, winc, o);
            if (threadIdx.x >= o) winc += t;
        }
        wtot[threadIdx.x] = winc - w;
    }
    __syncthreads();
    if (i < n) {
        int ex = inc - v + wtot[wid] + g_bsum[blockIdx.x];
        g_rowptr[i] = ex;
        g_cursor[i] = ex;
    }
}

__global__ void csr_scatter(RelPtrs rp) {
    int i = blockIdx.x * blockDim.x + threadIdx.x;
    if (i >= 4 * EDGES) return;
    int r = i / EDGES;
    int e = i - r * EDGES;
    int d = rp.dst[r][e];
    int pos = atomicAdd(&g_cursor[r * NP + d], 1);
    g_csrsrc[pos] = rp.src[r][e];
}

// ---------------- CSR aggregation v1 + fused ReLU ----------------------------
// One warp per dst node (serial per-edge loop; part of the measured 566.5us).
// acc = sum(ee*Wh[src]); out += acc / sum(ee). exp shift skipped (logits O(5),
// softmax shift-invariant). do_relu=1 on the LAST launch per output half
// applies ReLU in place (deg==0 rows included).
__global__ void edge_agg(const int* __restrict__ rowptr, const int* __restrict__ deg,
                         const float* __restrict__ es, const float* __restrict__ ed,
                         const float* __restrict__ Wh, float* __restrict__ out,
                         int do_relu)
{
    int gt = blockIdx.x * blockDim.x + threadIdx.x;
    int d = gt >> 5;
    if (d >= NP) return;
    int lane = gt & 31;
    int h = lane >> 3;
    int cnt = deg[d];
    float* op = out + (size_t)d * HD + lane * 4;
    if (cnt == 0) {
        if (do_relu) {
            float4 o = *(float4*)op;
            o.x = fmaxf(o.x, 0.f); o.y = fmaxf(o.y, 0.f);
            o.z = fmaxf(o.z, 0.f); o.w = fmaxf(o.w, 0.f);
            *(float4*)op = o;
        }
        return;
    }
    int beg = rowptr[d];
    float edh = ed[(size_t)d * NH + h];
    float ssum = 0.f;
    float ax = 0.f, ay = 0.f, az = 0.f, aw = 0.f;
    for (int e = beg; e < beg + cnt; e++) {
        int s = g_csrsrc[e];
        float eh = __expf(leaky(es[(size_t)s * NH + h] + edh));
        float4 v = *(const float4*)(Wh + (size_t)s * HD + lane * 4);
        ssum += eh;
        ax += eh * v.x; ay += eh * v.y; az += eh * v.z; aw += eh * v.w;
    }
    float inv = __frcp_rn(ssum);
    float4 o = *(float4*)op;
    o.x += ax * inv; o.y += ay * inv; o.z += az * inv; o.w += aw * inv;
    if (do_relu) {
        o.x = fmaxf(o.x, 0.f); o.y = fmaxf(o.y, 0.f);
        o.z = fmaxf(o.z, 0.f); o.w = fmaxf(o.w, 0.f);
    }
    *(float4*)op = o;
}

// -----------------------------------------------------------------------------
extern "C" void kernel_launch(void* const* d_in, const int* in_sizes, int n_in,
                              void* d_out, int out_size)
{
    const float* feat_P = (const float*)d_in[0];
    const float* feat_A = (const float*)d_in[1];
    const int* src[4] = { (const int*)d_in[2], (const int*)d_in[4],
                          (const int*)d_in[6], (const int*)d_in[8] };
    const int* dst[4] = { (const int*)d_in[3], (const int*)d_in[5],
                          (const int*)d_in[7], (const int*)d_in[9] };
    const float* W_P   = (const float*)d_in[10]; const float* b_P   = (const float*)d_in[11];
    const float* W_A   = (const float*)d_in[12]; const float* b_A   = (const float*)d_in[13];
    const float* W_p2p = (const float*)d_in[14]; const float* b_p2p = (const float*)d_in[15];
    const float* W_p2a = (const float*)d_in[16]; const float* b_p2a = (const float*)d_in[17];
    const float* W_a2p = (const float*)d_in[18]; const float* b_a2p = (const float*)d_in[19];
    const float* W_a2a = (const float*)d_in[20]; const float* b_a2a = (const float*)d_in[21];
    const float* att_src[4] = { (const float*)d_in[22], (const float*)d_in[24],
                                (const float*)d_in[26], (const float*)d_in[28] };
    const float* att_dst[4] = { (const float*)d_in[23], (const float*)d_in[25],
                                (const float*)d_in[27], (const float*)d_in[29] };

    float* out  = (float*)d_out;
    float* outP = out;
    float* outA = out + (size_t)NP * HD;

    float *whp2p, *whp2a, *wha2p, *wha2a, *esb, *edb;
    int *degp, *rowp;
    cudaGetSymbolAddress((void**)&whp2p, g_Whp2p);
    cudaGetSymbolAddress((void**)&whp2a, g_Whp2a);
    cudaGetSymbolAddress((void**)&wha2p, g_Wha2p);
    cudaGetSymbolAddress((void**)&wha2a, g_Wha2a);
    cudaGetSymbolAddress((void**)&esb,   g_es);
    cudaGetSymbolAddress((void**)&edb,   g_ed);
    cudaGetSymbolAddress((void**)&degp,  g_deg);
    cudaGetSymbolAddress((void**)&rowp,  g_rowptr);

    const size_t SMEM = (128 + 64) * PAD * sizeof(float);   // 101376
    cudaFuncSetAttribute(gemm_tc6, cudaFuncAttributeMaxDynamicSharedMemorySize, (int)SMEM);

    RelPtrs rp;
    for (int r = 0; r < 4; r++) { rp.src[r] = src[r]; rp.dst[r] = dst[r]; }

    // ---- CSR build (independent of GEMMs) ----
    const int N4  = 4 * NP;
    const int NB1 = (N4 + SCAN_B - 1) / SCAN_B;   // 391
    cudaMemsetAsync(degp, 0, N4 * sizeof(int));   // graph-capturable
    count_deg<<<(4 * EDGES + 255) / 256, 256>>>(rp);
    scan_p1<<<NB1, SCAN_B>>>(N4);
    scan_p2<<<1, 512>>>(NB1);
    scan_p3<<<NB1, SCAN_B>>>(N4);
    csr_scatter<<<(4 * EDGES + 255) / 256, 256>>>(rp);

    // ---- dense phase: all 6 GEMMs in one launch (blockIdx.y = job) ----
    const int GB = (NP + 127) / 128;
    const size_t T = (size_t)NP * NH;

    Jobs6 js;
    js.j[0] = { feat_P, W_P,   b_P,   att_dst[0], att_dst[2], outP,  nullptr, edb + 0 * T, edb + 2 * T };
    js.j[1] = { feat_A, W_A,   b_A,   att_dst[1], att_dst[3], outA,  nullptr, edb + 1 * T, edb + 3 * T };
    js.j[2] = { feat_P, W_p2p, b_p2p, att_src[0], nullptr,    whp2p, nullptr, esb + 0 * T, nullptr     };
    js.j[3] = { feat_P, W_p2a, b_p2a, att_src[1], nullptr,    whp2a, nullptr, esb + 1 * T, nullptr     };
    js.j[4] = { feat_A, W_a2p, b_a2p, att_src[2], nullptr,    wha2p, nullptr, esb + 2 * T, nullptr     };
    js.j[5] = { feat_A, W_a2a, b_a2a, att_src[3], nullptr,    wha2a, nullptr, esb + 3 * T, nullptr     };
    gemm_tc6<<<dim3(GB, 6), 256, SMEM>>>(NP, js);

    // ---- edge aggregation: atomic-free, per-relation; ReLU fused into the
    //      last launch targeting each output half ----
    const int AGG_B = (int)(((size_t)NP * 32 + 255) / 256);
    edge_agg<<<AGG_B, 256>>>(rowp + 0 * NP, degp + 0 * NP,
                             esb + 0 * T, edb + 0 * T, whp2p, outP, 0);
    edge_agg<<<AGG_B, 256>>>(rowp + 2 * NP, degp + 2 * NP,
                             esb + 2 * T, edb + 2 * T, wha2p, outP, 1);
    edge_agg<<<AGG_B, 256>>>(rowp + 1 * NP, degp + 1 * NP,
                             esb + 1 * T, edb + 1 * T, whp2a, outA, 0);
    edge_agg<<<AGG_B, 256>>>(rowp + 3 * NP, degp + 3 * NP,
                             esb + 3 * T, edb + 3 * T, wha2a, outA, 1);
}

// round 17
// speedup vs baseline: 1.3333x; 1.0628x over previous
#include <cuda_runtime.h>
#include <math_constants.h>

#define NP 100000          // nodes per type (N_P == N_A)
#define EDGES 500000
#define HD 128             // H*D
#define NH 4               // heads
#define PAD 132            // smem row stride (floats) to kill bank conflicts
#define SCAN_B 1024

// ---------------- scratch (device globals; no allocation allowed) ------------
__device__ float g_Whp2p[(size_t)NP*HD];
__device__ float g_Whp2a[(size_t)NP*HD];
__device__ float g_Wha2p[(size_t)NP*HD];
__device__ float g_Wha2a[(size_t)NP*HD];
__device__ float g_es[4*(size_t)NP*NH];   // per-relation src-node attn dots
__device__ float g_ed[4*(size_t)NP*NH];   // per-relation dst-node attn dots
__device__ int   g_deg   [4*NP];          // per-(relation,dst) in-degree
__device__ int   g_rowptr[4*NP];          // exclusive scan of g_deg
__device__ int   g_cursor[4*NP];          // scatter cursors (init = rowptr)
__device__ int   g_csrsrc[4*EDGES];       // src ids grouped by (relation,dst)
__device__ int   g_bsum  [512];           // block sums for the scan

// ---------------- helpers ----------------------------------------------------
__device__ __forceinline__ float leaky(float x) {
    return x > 0.f ? x : 0.2f * x;
}

__device__ __forceinline__ unsigned f2tf32(float f) {
    unsigned u;
    asm("cvt.rna.tf32.f32 %0, %1;" : "=r"(u) : "f"(f));
    return u;
}

__device__ __forceinline__ void mma_tf32(float d[4], const unsigned a[4],
                                         unsigned b0, unsigned b1) {
    asm volatile(
        "mma.sync.aligned.m16n8k8.row.col.f32.tf32.tf32.f32 "
        "{%0,%1,%2,%3}, {%4,%5,%6,%7}, {%8,%9}, {%0,%1,%2,%3};"
        : "+f"(d[0]), "+f"(d[1]), "+f"(d[2]), "+f"(d[3])
        : "r"(a[0]), "r"(a[1]), "r"(a[2]), "r"(a[3]), "r"(b0), "r"(b1));
}

// ---------------- 6-in-1 tensor-core GEMM (blockIdx.y = job) -----------------
// Measured as part of 528.9us: per-block body identical to the 47.6us/launch
// kernel; fusion removes 5 launch gaps + 5 partial-wave tails.
struct Job {
    const float *X, *W, *Bv, *att1, *att2;
    float *Wh, *acc2, *o1, *o2;
};
struct Jobs6 { Job j[6]; };

__global__ void __launch_bounds__(256, 2)
gemm_tc6(int M, Jobs6 jobs)
{
    extern __shared__ float sm[];
    float* As = sm;               // 128 x PAD (tf32 bit patterns), full K=128
    float* Ws = sm + 128 * PAD;   // 64 x PAD, one K-chunk of W
    const int tid  = threadIdx.x;
    const int row0 = blockIdx.x * 128;

    const Job jb = jobs.j[blockIdx.y];
    const float* __restrict__ X    = jb.X;
    const float* __restrict__ W    = jb.W;
    const float* __restrict__ Bv   = jb.Bv;
    const float* __restrict__ att1 = jb.att1;
    const float* __restrict__ att2 = jb.att2;
    float* __restrict__ Wh   = jb.Wh;
    float* __restrict__ acc2 = jb.acc2;
    float* __restrict__ o1   = jb.o1;
    float* __restrict__ o2   = jb.o2;

    // load X tile [128][128] -> tf32, zero-pad past M (4096 float4)
    #pragma unroll
    for (int i = 0; i < 16; i++) {
        int idx = tid + i * 256;
        int r = idx >> 5, c4 = idx & 31;
        int gr = row0 + r;
        float4 v = (gr < M) ? ((const float4*)X)[(size_t)gr * 32 + c4]
                            : make_float4(0.f, 0.f, 0.f, 0.f);
        float* d = As + r * PAD + c4 * 4;
        ((unsigned*)d)[0] = f2tf32(v.x);
        ((unsigned*)d)[1] = f2tf32(v.y);
        ((unsigned*)d)[2] = f2tf32(v.z);
        ((unsigned*)d)[3] = f2tf32(v.w);
    }

    const int wid   = tid >> 5;
    const int lane  = tid & 31;
    const int warpM = wid & 3;
    const int warpN = wid >> 2;
    const int wm    = warpM * 32;
    const int wn    = warpN * 64;
    const int g     = lane >> 2;
    const int tig   = lane & 3;

    const unsigned* Au = (const unsigned*)As;
    const unsigned* Wu = (const unsigned*)Ws;

    float acc[2][8][4];
    #pragma unroll
    for (int mi = 0; mi < 2; mi++)
        #pragma unroll
        for (int ni = 0; ni < 8; ni++)
            #pragma unroll
            for (int q = 0; q < 4; q++) acc[mi][ni][q] = 0.f;

    #pragma unroll
    for (int kh = 0; kh < 2; kh++) {
        __syncthreads();
        #pragma unroll
        for (int i = 0; i < 8; i++) {
            int idx = tid + i * 256;
            int r = idx >> 5, c4 = idx & 31;
            float4 v = ((const float4*)W)[idx + kh * 2048];
            float* d = Ws + r * PAD + c4 * 4;
            ((unsigned*)d)[0] = f2tf32(v.x);
            ((unsigned*)d)[1] = f2tf32(v.y);
            ((unsigned*)d)[2] = f2tf32(v.z);
            ((unsigned*)d)[3] = f2tf32(v.w);
        }
        __syncthreads();

        #pragma unroll
        for (int kkk = 0; kkk < 8; kkk++) {
            const int k0  = kh * 64 + kkk * 8;
            const int k0l = kkk * 8;
            unsigned a[2][4];
            #pragma unroll
            for (int mi = 0; mi < 2; mi++) {
                int rb = wm + mi * 16;
                a[mi][0] = Au[(rb + g    ) * PAD + k0 + tig];
                a[mi][1] = Au[(rb + g + 8) * PAD + k0 + tig];
                a[mi][2] = Au[(rb + g    ) * PAD + k0 + tig + 4];
                a[mi][3] = Au[(rb + g + 8) * PAD + k0 + tig + 4];
            }
            #pragma unroll
            for (int ni = 0; ni < 8; ni++) {
                unsigned b0 = Wu[(k0l + tig    ) * PAD + wn + ni * 8 + g];
                unsigned b1 = Wu[(k0l + tig + 4) * PAD + wn + ni * 8 + g];
                mma_tf32(acc[0][ni], a[0], b0, b1);
                mma_tf32(acc[1][ni], a[1], b0, b1);
            }
        }
    }

    float pa[2][2][2][2];
    #pragma unroll
    for (int v = 0; v < 2; v++)
        #pragma unroll
        for (int mi = 0; mi < 2; mi++)
            #pragma unroll
            for (int hf = 0; hf < 2; hf++)
                #pragma unroll
                for (int hl = 0; hl < 2; hl++) pa[v][mi][hf][hl] = 0.f;

    #pragma unroll
    for (int ni = 0; ni < 8; ni++) {
        const int c0 = wn + ni * 8 + 2 * tig;
        const int hl = ni >> 2;
        const float b0 = __ldg(Bv + c0), b1 = __ldg(Bv + c0 + 1);
        float a10 = 0.f, a11 = 0.f, a20 = 0.f, a21 = 0.f;
        if (att1) { a10 = __ldg(att1 + c0); a11 = __ldg(att1 + c0 + 1); }
        if (att2) { a20 = __ldg(att2 + c0); a21 = __ldg(att2 + c0 + 1); }
        #pragma unroll
        for (int mi = 0; mi < 2; mi++) {
            int r0 = row0 + wm + mi * 16 + g;
            float y00 = acc[mi][ni][0] + b0, y01 = acc[mi][ni][1] + b1;
            float y10 = acc[mi][ni][2] + b0, y11 = acc[mi][ni][3] + b1;
            if (r0 < M) {
                *(float2*)(Wh + (size_t)r0 * HD + c0) = make_float2(y00, y01);
                if (acc2) *(float2*)(acc2 + (size_t)r0 * HD + c0) = make_float2(y00, y01);
            }
            if (r0 + 8 < M) {
                *(float2*)(Wh + (size_t)(r0 + 8) * HD + c0) = make_float2(y10, y11);
                if (acc2) *(float2*)(acc2 + (size_t)(r0 + 8) * HD + c0) = make_float2(y10, y11);
            }
            pa[0][mi][0][hl] += y00 * a10 + y01 * a11;
            pa[0][mi][1][hl] += y10 * a10 + y11 * a11;
            pa[1][mi][0][hl] += y00 * a20 + y01 * a21;
            pa[1][mi][1][hl] += y10 * a20 + y11 * a21;
        }
    }

    #pragma unroll
    for (int v = 0; v < 2; v++) {
        float* o = (v == 0) ? o1 : o2;
        if (!o) continue;
        #pragma unroll
        for (int mi = 0; mi < 2; mi++)
            #pragma unroll
            for (int hf = 0; hf < 2; hf++)
                #pragma unroll
                for (int hl = 0; hl < 2; hl++) {
                    float p = pa[v][mi][hf][hl];
                    p += __shfl_down_sync(0xffffffffu, p, 2, 4);
                    p += __shfl_down_sync(0xffffffffu, p, 1, 4);
                    if (tig == 0) {
                        int r = row0 + wm + mi * 16 + hf * 8 + g;
                        if (r < M) o[(size_t)r * NH + warpN * 2 + hl] = p;
                    }
                }
    }
}

// ---------------- CSR construction (all 4 relations concatenated) ------------
struct RelPtrs {
    const int* src[4];
    const int* dst[4];
};

__global__ void count_deg(RelPtrs rp) {
    int i = blockIdx.x * blockDim.x + threadIdx.x;
    if (i >= 4 * EDGES) return;
    int r = i / EDGES;
    int e = i - r * EDGES;
    atomicAdd(&g_deg[r * NP + rp.dst[r][e]], 1);
}

__global__ void scan_p1(int n) {
    __shared__ int wtot[32];
    int i = blockIdx.x * SCAN_B + threadIdx.x;
    int v = (i < n) ? g_deg[i] : 0;
    #pragma unroll
    for (int o = 16; o; o >>= 1) v += __shfl_down_sync(0xffffffffu, v, o);
    if ((threadIdx.x & 31) == 0) wtot[threadIdx.x >> 5] = v;
    __syncthreads();
    if (threadIdx.x < 32) {
        int w = wtot[threadIdx.x];
        #pragma unroll
        for (int o = 16; o; o >>= 1) w += __shfl_down_sync(0xffffffffu, w, o);
        if (threadIdx.x == 0) g_bsum[blockIdx.x] = w;
    }
}

__global__ void scan_p2(int nb) {
    __shared__ int wtot[16];
    int tid = threadIdx.x;
    int lane = tid & 31, wid = tid >> 5;
    int v = (tid < nb) ? g_bsum[tid] : 0;
    int inc = v;
    #pragma unroll
    for (int o = 1; o < 32; o <<= 1) {
        int t = __shfl_up_sync(0xffffffffu, inc, o);
        if (lane >= o) inc += t;
    }
    if (lane == 31) wtot[wid] = inc;
    __syncthreads();
    if (tid < 16) {
        int w = wtot[tid];
        int winc = w;
        #pragma unroll
        for (int o = 1; o < 16; o <<= 1) {
            int t = __shfl_up_sync(0x0000ffffu, winc, o);
            if (tid >= o) winc += t;
        }
        wtot[tid] = winc - w;
    }
    __syncthreads();
    if (tid < nb) g_bsum[tid] = inc - v + wtot[wid];
}

__global__ void scan_p3(int n) {
    __shared__ int wtot[32];
    int i = blockIdx.x * SCAN_B + threadIdx.x;
    int lane = threadIdx.x & 31, wid = threadIdx.x >> 5;
    int v = (i < n) ? g_deg[i] : 0;
    int inc = v;
    #pragma unroll
    for (int o = 1; o < 32; o <<= 1) {
        int t = __shfl_up_sync(0xffffffffu, inc, o);
        if (lane >= o) inc += t;
    }
    if (lane == 31) wtot[wid] = inc;
    __syncthreads();
    if (threadIdx.x < 32) {
        int w = wtot[threadIdx.x];
        int winc = w;
        #pragma unroll
        for (int o = 1; o < 32; o <<= 1) {
            int t = __shfl_up_sync(0xffffffffu, winc, o);
            if (threadIdx.x >= o) winc += t;
        }
        wtot[threadIdx.x] = winc - w;
    }
    __syncthreads();
    if (i < n) {
        int ex = inc - v + wtot[wid] + g_bsum[blockIdx.x];
        g_rowptr[i] = ex;
        g_cursor[i] = ex;
    }
}

__global__ void csr_scatter(RelPtrs rp) {
    int i = blockIdx.x * blockDim.x + threadIdx.x;
    if (i >= 4 * EDGES) return;
    int r = i / EDGES;
    int e = i - r * EDGES;
    int d = rp.dst[r][e];
    int pos = atomicAdd(&g_cursor[r * NP + d], 1);
    g_csrsrc[pos] = rp.src[r][e];
}

// ---------------- paired CSR aggregation + ReLU ------------------------------
// One warp per dst; BOTH relations feeding this output half are accumulated
// in one pass, so the output half is RMW'd ONCE (was twice) -> saves 102MB of
// L2 traffic per half + 2 launch gaps. exp shift skipped (logits O(5),
// softmax shift-invariant).
__global__ void edge_agg2(const int* __restrict__ rowA, const int* __restrict__ degA,
                          const float* __restrict__ esA, const float* __restrict__ edA,
                          const float* __restrict__ WhA,
                          const int* __restrict__ rowB, const int* __restrict__ degB,
                          const float* __restrict__ esB, const float* __restrict__ edB,
                          const float* __restrict__ WhB,
                          float* __restrict__ out)
{
    int gt = blockIdx.x * blockDim.x + threadIdx.x;
    int d = gt >> 5;
    if (d >= NP) return;
    int lane = gt & 31;
    int h = lane >> 3;

    float rx = 0.f, ry = 0.f, rz = 0.f, rw = 0.f;

    int cntA = degA[d];
    if (cntA > 0) {
        int beg = rowA[d];
        float edh = edA[(size_t)d * NH + h];
        float ssum = 0.f, ax = 0.f, ay = 0.f, az = 0.f, aw = 0.f;
        for (int e = beg; e < beg + cntA; e++) {
            int s = g_csrsrc[e];
            float eh = __expf(leaky(esA[(size_t)s * NH + h] + edh));
            float4 v = *(const float4*)(WhA + (size_t)s * HD + lane * 4);
            ssum += eh;
            ax += eh * v.x; ay += eh * v.y; az += eh * v.z; aw += eh * v.w;
        }
        float inv = __frcp_rn(ssum);
        rx += ax * inv; ry += ay * inv; rz += az * inv; rw += aw * inv;
    }

    int cntB = degB[d];
    if (cntB > 0) {
        int beg = rowB[d];
        float edh = edB[(size_t)d * NH + h];
        float ssum = 0.f, ax = 0.f, ay = 0.f, az = 0.f, aw = 0.f;
        for (int e = beg; e < beg + cntB; e++) {
            int s = g_csrsrc[e];
            float eh = __expf(leaky(esB[(size_t)s * NH + h] + edh));
            float4 v = *(const float4*)(WhB + (size_t)s * HD + lane * 4);
            ssum += eh;
            ax += eh * v.x; ay += eh * v.y; az += eh * v.z; aw += eh * v.w;
        }
        float inv = __frcp_rn(ssum);
        rx += ax * inv; ry += ay * inv; rz += az * inv; rw += aw * inv;
    }

    float* op = out + (size_t)d * HD + lane * 4;
    float4 o = *(float4*)op;
    o.x = fmaxf(o.x + rx, 0.f);
    o.y = fmaxf(o.y + ry, 0.f);
    o.z = fmaxf(o.z + rz, 0.f);
    o.w = fmaxf(o.w + rw, 0.f);
    *(float4*)op = o;
}

// -----------------------------------------------------------------------------
extern "C" void kernel_launch(void* const* d_in, const int* in_sizes, int n_in,
                              void* d_out, int out_size)
{
    const float* feat_P = (const float*)d_in[0];
    const float* feat_A = (const float*)d_in[1];
    const int* src[4] = { (const int*)d_in[2], (const int*)d_in[4],
                          (const int*)d_in[6], (const int*)d_in[8] };
    const int* dst[4] = { (const int*)d_in[3], (const int*)d_in[5],
                          (const int*)d_in[7], (const int*)d_in[9] };
    const float* W_P   = (const float*)d_in[10]; const float* b_P   = (const float*)d_in[11];
    const float* W_A   = (const float*)d_in[12]; const float* b_A   = (const float*)d_in[13];
    const float* W_p2p = (const float*)d_in[14]; const float* b_p2p = (const float*)d_in[15];
    const float* W_p2a = (const float*)d_in[16]; const float* b_p2a = (const float*)d_in[17];
    const float* W_a2p = (const float*)d_in[18]; const float* b_a2p = (const float*)d_in[19];
    const float* W_a2a = (const float*)d_in[20]; const float* b_a2a = (const float*)d_in[21];
    const float* att_src[4] = { (const float*)d_in[22], (const float*)d_in[24],
                                (const float*)d_in[26], (const float*)d_in[28] };
    const float* att_dst[4] = { (const float*)d_in[23], (const float*)d_in[25],
                                (const float*)d_in[27], (const float*)d_in[29] };

    float* out  = (float*)d_out;
    float* outP = out;
    float* outA = out + (size_t)NP * HD;

    float *whp2p, *whp2a, *wha2p, *wha2a, *esb, *edb;
    int *degp, *rowp;
    cudaGetSymbolAddress((void**)&whp2p, g_Whp2p);
    cudaGetSymbolAddress((void**)&whp2a, g_Whp2a);
    cudaGetSymbolAddress((void**)&wha2p, g_Wha2p);
    cudaGetSymbolAddress((void**)&wha2a, g_Wha2a);
    cudaGetSymbolAddress((void**)&esb,   g_es);
    cudaGetSymbolAddress((void**)&edb,   g_ed);
    cudaGetSymbolAddress((void**)&degp,  g_deg);
    cudaGetSymbolAddress((void**)&rowp,  g_rowptr);

    const size_t SMEM = (128 + 64) * PAD * sizeof(float);   // 101376
    cudaFuncSetAttribute(gemm_tc6, cudaFuncAttributeMaxDynamicSharedMemorySize, (int)SMEM);

    RelPtrs rp;
    for (int r = 0; r < 4; r++) { rp.src[r] = src[r]; rp.dst[r] = dst[r]; }

    // ---- CSR build ----
    const int N4  = 4 * NP;
    const int NB1 = (N4 + SCAN_B - 1) / SCAN_B;   // 391
    cudaMemsetAsync(degp, 0, N4 * sizeof(int));   // graph-capturable
    count_deg<<<(4 * EDGES + 255) / 256, 256>>>(rp);
    scan_p1<<<NB1, SCAN_B>>>(N4);
    scan_p2<<<1, 512>>>(NB1);
    scan_p3<<<NB1, SCAN_B>>>(N4);
    csr_scatter<<<(4 * EDGES + 255) / 256, 256>>>(rp);

    // ---- dense phase: all 6 GEMMs in one launch (blockIdx.y = job) ----
    const int GB = (NP + 127) / 128;
    const size_t T = (size_t)NP * NH;

    Jobs6 js;
    js.j[0] = { feat_P, W_P,   b_P,   att_dst[0], att_dst[2], outP,  nullptr, edb + 0 * T, edb + 2 * T };
    js.j[1] = { feat_A, W_A,   b_A,   att_dst[1], att_dst[3], outA,  nullptr, edb + 1 * T, edb + 3 * T };
    js.j[2] = { feat_P, W_p2p, b_p2p, att_src[0], nullptr,    whp2p, nullptr, esb + 0 * T, nullptr     };
    js.j[3] = { feat_P, W_p2a, b_p2a, att_src[1], nullptr,    whp2a, nullptr, esb + 1 * T, nullptr     };
    js.j[4] = { feat_A, W_a2p, b_a2p, att_src[2], nullptr,    wha2p, nullptr, esb + 2 * T, nullptr     };
    js.j[5] = { feat_A, W_a2a, b_a2a, att_src[3], nullptr,    wha2a, nullptr, esb + 3 * T, nullptr     };
    gemm_tc6<<<dim3(GB, 6), 256, SMEM>>>(NP, js);

    // ---- edge aggregation: one launch per output half (both relations
    //      accumulated in-kernel; single out RMW + fused ReLU) ----
    const int AGG_B = (int)(((size_t)NP * 32 + 255) / 256);
    // outP <- rel 0 (p2p, Wh=whp2p) + rel 2 (a2p, Wh=wha2p)
    edge_agg2<<<AGG_B, 256>>>(rowp + 0 * NP, degp + 0 * NP,
                              esb + 0 * T, edb + 0 * T, whp2p,
                              rowp + 2 * NP, degp + 2 * NP,
                              esb + 2 * T, edb + 2 * T, wha2p,
                              outP);
    // outA <- rel 1 (p2a, Wh=whp2a) + rel 3 (a2a, Wh=wha2a)
    edge_agg2<<<AGG_B, 256>>>(rowp + 1 * NP, degp + 1 * NP,
                              esb + 1 * T, edb + 1 * T, whp2a,
                              rowp + 3 * NP, degp + 3 * NP,
                              esb + 3 * T, edb + 3 * T, wha2a,
                              outA);
}